// round 5
// baseline (speedup 1.0000x reference)
#include <cuda_runtime.h>

#define N 8192
#define ROWS_PER_BLK 32
#define COLS_PER_BLK 1024
#define CB 8      /* column tiles: 8192/1024 */
#define RB 256    /* row tiles:    8192/32   */
#define THREADS 256
#define CHUNKS 32 /* combine1 chunks over RB (8 rb each) */

// Scratch (no device allocation allowed -> __device__ globals)
__device__ float g_rowpart[CB * N];       // [cb][row]  partial row sums (256 KB)
__device__ float g_colpart[RB * N];       // [rb][col]  partial col sums (8 MiB)
__device__ float g_cpart2[CHUNKS * N];    // folded col partials (1 MiB)
__device__ float g_blocksum[32];
__device__ int   g_cnt_final;

// ---------------------------------------------------------------------------
// Pass 1: one block per 32x1024 tile -> 2048 blocks. Streaming single read of
// the 256 MiB matrix (proven ~41 us / ~6.5 TB/s in R4 profile).
// ---------------------------------------------------------------------------
__global__ void __launch_bounds__(THREADS)
tile_kernel(const float* __restrict__ flow)
{
    const int cb   = blockIdx.x;          // 0..7
    const int rb   = blockIdx.y;          // 0..255
    const int t    = threadIdx.x;         // 0..255
    const int warp = t >> 5;
    const int lane = t & 31;
    const int row0 = rb * ROWS_PER_BLK;
    const int col0 = cb * COLS_PER_BLK;

    __shared__ float s_row[ROWS_PER_BLK][32];   // [row][warp*4 + sublane] 4 KB

    float4 c0 = make_float4(0.f, 0.f, 0.f, 0.f);

    const float4* base = reinterpret_cast<const float4*>(flow)
                         + (size_t)row0 * (N / 4) + (col0 / 4);

    #pragma unroll 4
    for (int r = 0; r < ROWS_PER_BLK; ++r) {
        float4 a = __ldcs(base + (size_t)r * (N / 4) + t);   // streaming

        c0.x += a.x; c0.y += a.y; c0.z += a.z; c0.w += a.w;

        // partial row reduce: 32 lanes -> 4 partials (3 shuffles)
        float s = (a.x + a.y) + (a.z + a.w);
        s += __shfl_xor_sync(0xffffffffu, s, 16);
        s += __shfl_xor_sync(0xffffffffu, s, 8);
        s += __shfl_xor_sync(0xffffffffu, s, 4);
        if (lane < 4) s_row[r][warp * 4 + lane] = s;
    }

    // Column partials: unique writer per (rb, col) -> plain store, no atomics
    reinterpret_cast<float4*>(g_colpart + (size_t)rb * N + col0)[t] = c0;

    __syncthreads();

    // Row fold: 8 threads per row (aligned 8-lane groups).
    {
        const int r = t >> 3;
        const int j = (t & 7) * 4;
        float s = (s_row[r][j] + s_row[r][j + 1])
                + (s_row[r][j + 2] + s_row[r][j + 3]);
        s += __shfl_xor_sync(0xffffffffu, s, 4);
        s += __shfl_xor_sync(0xffffffffu, s, 2);
        s += __shfl_xor_sync(0xffffffffu, s, 1);
        if ((t & 7) == 0) g_rowpart[cb * N + row0 + r] = s;
    }
}

// ---------------------------------------------------------------------------
// Pass 2: 1024 blocks = (32 col groups) x (32 rb-chunks). Each block folds
// 8 rb-partials for 256 columns: 8 independent coalesced loads per thread.
// High MLP -> DRAM-rate fold of the 8 MiB scratch.
// ---------------------------------------------------------------------------
__global__ void __launch_bounds__(256)
combine1_kernel(void)
{
    const int t  = threadIdx.x;
    const int bx = blockIdx.x;     // column group 0..31
    const int by = blockIdx.y;     // rb chunk     0..31
    const int i  = bx * 256 + t;

    float cs = 0.f;
    #pragma unroll
    for (int j = 0; j < RB / CHUNKS; ++j)
        cs += g_colpart[(size_t)(by * (RB / CHUNKS) + j) * N + i];

    g_cpart2[by * N + i] = cs;
}

// ---------------------------------------------------------------------------
// Pass 3: 32 blocks. Per column fold 32 chunk partials + 8 row partials
// (1.25 MiB, L2-hot), |.|, block reduce; globally-last block (int counter,
// self-resetting for graph replay) folds the 32 scalars -> out.
// ---------------------------------------------------------------------------
__global__ void __launch_bounds__(256)
final_kernel(float* __restrict__ out)
{
    const int t = threadIdx.x;
    const int i = blockIdx.x * 256 + t;

    float cs = 0.f;
    #pragma unroll
    for (int p = 0; p < CHUNKS; ++p) cs += g_cpart2[p * N + i];

    float rs = 0.f;
    #pragma unroll
    for (int cb = 0; cb < CB; ++cb) rs += g_rowpart[cb * N + i];

    float v = fabsf(rs - cs);
    v += __shfl_xor_sync(0xffffffffu, v, 16);
    v += __shfl_xor_sync(0xffffffffu, v, 8);
    v += __shfl_xor_sync(0xffffffffu, v, 4);
    v += __shfl_xor_sync(0xffffffffu, v, 2);
    v += __shfl_xor_sync(0xffffffffu, v, 1);

    __shared__ float sw[8];
    if ((t & 31) == 0) sw[t >> 5] = v;
    __syncthreads();

    __shared__ int s_fin;
    if (t == 0) {
        float w = ((sw[0] + sw[1]) + (sw[2] + sw[3]))
                + ((sw[4] + sw[5]) + (sw[6] + sw[7]));
        g_blocksum[blockIdx.x] = w;
        __threadfence();
        s_fin = (atomicAdd(&g_cnt_final, 1) == 31);
    }
    __syncthreads();
    if (!s_fin) return;
    __threadfence();

    if (t < 32) {
        float v2 = g_blocksum[t];
        v2 += __shfl_xor_sync(0xffffffffu, v2, 16);
        v2 += __shfl_xor_sync(0xffffffffu, v2, 8);
        v2 += __shfl_xor_sync(0xffffffffu, v2, 4);
        v2 += __shfl_xor_sync(0xffffffffu, v2, 2);
        v2 += __shfl_xor_sync(0xffffffffu, v2, 1);
        if (t == 0) {
            out[0] = v2;
            g_cnt_final = 0;   // reset for next graph replay
        }
    }
}

extern "C" void kernel_launch(void* const* d_in, const int* in_sizes, int n_in,
                              void* d_out, int out_size)
{
    (void)in_sizes; (void)n_in; (void)out_size;
    const float* flow = (const float*)d_in[0];
    float* out = (float*)d_out;

    tile_kernel<<<dim3(CB, RB), THREADS>>>(flow);
    combine1_kernel<<<dim3(32, CHUNKS), 256>>>();
    final_kernel<<<32, 256>>>(out);
}